// round 6
// baseline (speedup 1.0000x reference)
#include <cuda_runtime.h>
#include <cuda_fp16.h>
#include <cstdint>

// ---- SMEM layout (bytes): 7 x 32KB unpadded swizzled fp16 tiles + small ----
#define OFF_OUTA 0
#define OFF_OUTB 32768
#define OFF_HA   65536
#define OFF_HB   98304
#define OFF_WIM  131072
#define OFF_W1   163840
#define OFF_W2   196608
#define OFF_C0   229376   // float2 (wz,bi)[128] = 1KB ; ALIASED as sO2 float[256]
#define OFF_WF   230400   // float[128]
#define OFF_B12  230912   // float2 (b1,b2)[128] = 1KB
#define SMEM_TOTAL 231936

#define NT_T 7            // tensor covers cols 0..111 (7 nt per n-warp), FMA cols 112..127

// ---- device scratch ----
__device__ __half g_WiM[(size_t)128 * 16384];  // per-i swizzled 128x128 fp16 image
__device__ float  g_wz[128 * 128];
__device__ __half g_W1h[16384];                // swizzled image
__device__ __half g_W2h[16384];
__device__ float  g_zT[(size_t)128 * 131072];  // [i][b]

// XOR-swizzled byte offset in a 128x128 fp16 tile (row = 256B)
__host__ __device__ __forceinline__ uint32_t tile_off(int r, int c) {
    return (uint32_t)(r * 256 + ((c * 2) ^ ((r & 7) << 4)));
}

// ---- prologue kernels ----
__global__ void prep_weights(const float* __restrict__ Wi, const float* __restrict__ M,
                             const float* __restrict__ W1, const float* __restrict__ W2) {
    int i = blockIdx.x;
    if (i < 128) {
        const float* Wii = Wi + (size_t)i * 16512;   // 128*129
        for (int v = threadIdx.x; v < 16384; v += blockDim.x) {
            int j = v >> 7, k = v & 127;
            float m = (k == i) ? 0.f : M[k * 128 + i];
            g_WiM[(size_t)i * 16384 + (tile_off(j, k) >> 1)] = __float2half(Wii[j * 129 + k] * m);
        }
        for (int j = threadIdx.x; j < 128; j += blockDim.x)
            g_wz[i * 128 + j] = Wii[j * 129 + 128];
    } else if (i == 128) {
        for (int v = threadIdx.x; v < 16384; v += blockDim.x)
            g_W1h[tile_off(v >> 7, v & 127) >> 1] = __float2half(W1[v]);
    } else {
        for (int v = threadIdx.x; v < 16384; v += blockDim.x)
            g_W2h[tile_off(v >> 7, v & 127) >> 1] = __float2half(W2[v]);
    }
}

__global__ void transpose_z(const float* __restrict__ z, int Bn) {
    __shared__ float t[32][33];
    int b0 = blockIdx.x * 32, i0 = blockIdx.y * 32;
    #pragma unroll
    for (int r = threadIdx.y; r < 32; r += 8)
        t[r][threadIdx.x] = z[(size_t)(b0 + r) * 128 + i0 + threadIdx.x];
    __syncthreads();
    #pragma unroll
    for (int r = threadIdx.y; r < 32; r += 8)
        g_zT[(size_t)(i0 + r) * Bn + b0 + threadIdx.x] = t[threadIdx.x][r];
}

// ---- mma helpers ----
__device__ __forceinline__ void ldsm4(uint32_t addr, uint32_t* r) {
    asm volatile("ldmatrix.sync.aligned.m8n8.x4.shared.b16 {%0,%1,%2,%3},[%4];"
        : "=r"(r[0]), "=r"(r[1]), "=r"(r[2]), "=r"(r[3]) : "r"(addr));
}
__device__ __forceinline__ void mma16816(float* c, const uint32_t* a, const uint32_t* b) {
    asm volatile("mma.sync.aligned.m16n8k16.row.col.f32.f16.f16.f32 "
        "{%0,%1,%2,%3},{%4,%5,%6,%7},{%8,%9},{%0,%1,%2,%3};"
        : "+f"(c[0]), "+f"(c[1]), "+f"(c[2]), "+f"(c[3])
        : "r"(a[0]), "r"(a[1]), "r"(a[2]), "r"(a[3]), "r"(b[0]), "r"(b[1]));
}
__device__ __forceinline__ void cpa16(uint32_t s, const void* g) {
    asm volatile("cp.async.cg.shared.global [%0],[%1],16;" :: "r"(s), "l"(g));
}

// dual-tile tensor GEMM over cols 0..111: C{a,b} = A{a,b} * B^T, B loaded once/kstep
__device__ __forceinline__ void gemm2x(uint32_t aBaseA, uint32_t aBaseB, uint32_t bBase,
                                       int lane, int mrow, int ncol,
                                       float accA[2][NT_T][4], float accB[2][NT_T][4]) {
    #pragma unroll
    for (int mt = 0; mt < 2; mt++)
        #pragma unroll
        for (int nt = 0; nt < NT_T; nt++)
            #pragma unroll
            for (int c = 0; c < 4; c++) { accA[mt][nt][c] = 0.f; accB[mt][nt][c] = 0.f; }

    const int rA = mrow + (lane & 15);
    const uint32_t rowA0 = aBaseA + (uint32_t)(rA * 256);
    const uint32_t rowB0 = aBaseB + (uint32_t)(rA * 256);
    const uint32_t xorA = (uint32_t)((rA & 7) << 4);
    const uint32_t cA = (lane & 16) ? 16u : 0u;
    const int rB = ncol + (lane & 7) + ((lane & 16) ? 8 : 0);
    const uint32_t rowW = bBase + (uint32_t)(rB * 256);
    const uint32_t xorB = (uint32_t)((lane & 7) << 4);
    const uint32_t cB = (lane & 8) ? 16u : 0u;

    #pragma unroll
    for (int ks = 0; ks < 8; ks++) {
        uint32_t offA = ((uint32_t)(ks * 32) + cA) ^ xorA;
        uint32_t offB = ((uint32_t)(ks * 32) + cB) ^ xorB;
        uint32_t a0[4], a1[4], c0[4], c1[4], b[16];
        ldsm4(rowA0 + offA, a0);
        ldsm4(rowA0 + 4096 + offA, a1);
        ldsm4(rowB0 + offA, c0);
        ldsm4(rowB0 + 4096 + offA, c1);
        #pragma unroll
        for (int q = 0; q < 4; q++) ldsm4(rowW + (uint32_t)(q * 4096) + offB, b + 4 * q);
        #pragma unroll
        for (int nt = 0; nt < NT_T; nt++) {
            const uint32_t* bb = b + (nt >> 1) * 4 + (nt & 1) * 2;
            mma16816(accA[0][nt], a0, bb);
            mma16816(accA[1][nt], a1, bb);
            mma16816(accB[0][nt], c0, bb);
            mma16816(accB[1][nt], c1, bb);
        }
    }
}

// FMA-pipe GEMM for cols 112..127, this thread's own row.
// acc2[c]: lane-halves accumulate even/odd k separately (two K=64 fp16 chains).
__device__ __forceinline__ void fma_cols(const char* sm, uint32_t aImgOff, uint32_t wImgOff,
                                         int rl, __half2 acc2[16]) {
    #pragma unroll
    for (int c = 0; c < 16; c++) acc2[c] = __floats2half2_rn(0.f, 0.f);
    const uint32_t xr = (uint32_t)((rl & 7) << 4);
    const char* aRow = sm + aImgOff + rl * 256;
    #pragma unroll
    for (int ks = 0; ks < 16; ks++) {
        uint4 av = *(const uint4*)(aRow + (((uint32_t)(ks * 16)) ^ xr));
        const __half2* a2 = (const __half2*)&av;
        #pragma unroll
        for (int c = 0; c < 16; c++) {
            const int wc = 112 + c;
            uint4 wv = *(const uint4*)(sm + wImgOff + wc * 256
                                       + (((uint32_t)(ks * 16)) ^ ((uint32_t)((wc & 7) << 4))));
            const __half2* w2 = (const __half2*)&wv;
            acc2[c] = __hfma2(a2[0], w2[0], acc2[c]);
            acc2[c] = __hfma2(a2[1], w2[1], acc2[c]);
            acc2[c] = __hfma2(a2[2], w2[2], acc2[c]);
            acc2[c] = __hfma2(a2[3], w2[3], acc2[c]);
        }
    }
}

// ---- main kernel: 1 CTA = 2 batch tiles of 128, hybrid HMMA(112) + FMA(16) ----
__global__ __launch_bounds__(256, 1)
void gen_main(const float* __restrict__ x,  const float* __restrict__ bi,
              const float* __restrict__ Wf, const float* __restrict__ bf,
              const float* __restrict__ b1, const float* __restrict__ b2,
              float* __restrict__ out, int Bn)
{
    extern __shared__ char sm[];
    const int tid = threadIdx.x, lane = tid & 31, wid = tid >> 5;
    const int wm = wid >> 1, wn = wid & 1;
    const int mrow = wm * 32, ncol = wn * 56;       // tensor n-warp covers 56 cols
    const int gr0 = lane >> 2, gc0 = 2 * (lane & 3);
    const size_t b0 = (size_t)blockIdx.x * 256;
    const int rl = tid & 127;                        // own row (local), tile = tid>>7
    const uint32_t ownTileOut = (tid >> 7) ? OFF_OUTB : OFF_OUTA;
    const uint32_t ownTileH   = (tid >> 7) ? OFF_HB  : OFF_HA;
    const uint32_t xrOwn = (uint32_t)((rl & 7) << 4);

    const uint32_t smBase = (uint32_t)__cvta_generic_to_shared(sm);
    const uint32_t aOutA = smBase + OFF_OUTA, aOutB = smBase + OFF_OUTB;
    const uint32_t aHA = smBase + OFF_HA, aHB = smBase + OFF_HB;
    const uint32_t aWiM = smBase + OFF_WIM, aW1 = smBase + OFF_W1, aW2 = smBase + OFF_W2;
    float2* sC0  = (float2*)(sm + OFF_C0);
    float*  sO2  = (float*)(sm + OFF_C0);      // alias; disjoint lifetime within step
    float*  sWf  = (float*)(sm + OFF_WF);
    float2* sB12 = (float2*)(sm + OFF_B12);

    // ---- stage x into both tiles (fp16, swizzled) ----
    const float4* xg = (const float4*)(x + b0 * 128);
    #pragma unroll
    for (int q = 0; q < 32; q++) {
        int v = (q << 8) + tid;
        float4 f = xg[v];
        int rv = v >> 5, c4 = (v & 31) << 2;
        uint32_t off = tile_off(rv & 127, c4);
        char* base = sm + ((rv >> 7) ? OFF_OUTB : OFF_OUTA);
        *(__half2*)(base + off)     = __floats2half2_rn(f.x, f.y);
        *(__half2*)(base + off + 4) = __floats2half2_rn(f.z, f.w);
    }
    // ---- stage W1/W2 (pre-swizzled) + WiM(0) ----
    #pragma unroll
    for (int q = 0; q < 8; q++) {
        int v = (q << 8) + tid;
        ((uint4*)(sm + OFF_W1))[v] = ((const uint4*)g_W1h)[v];
        ((uint4*)(sm + OFF_W2))[v] = ((const uint4*)g_W2h)[v];
        cpa16(aWiM + (uint32_t)(v << 4), ((const uint4*)g_WiM) + v);
    }
    asm volatile("cp.async.commit_group;");
    if (tid < 128) sB12[tid] = make_float2(b1[tid], b2[tid]);
    asm volatile("cp.async.wait_group 0;");
    __syncthreads();

    float accA[2][NT_T][4], accB[2][NT_T][4];
    __half2 acc2[16];

    for (int i = 0; i < 128; i++) {
        if (tid < 128) {
            sC0[tid] = make_float2(g_wz[(i << 7) + tid], bi[(i << 7) + tid]);
            sWf[tid] = Wf[(i << 7) + tid];
        }
        const float bfi = bf[i];
        const float* zg = g_zT + (size_t)i * Bn + b0;
        const float zOwn = zg[tid];
        __syncthreads();

        // ---- G0: tensor cols 0..111 + FMA cols 112..127 ----
        gemm2x(aOutA, aOutB, aWiM, lane, mrow, ncol, accA, accB);
        fma_cols(sm, ownTileOut, OFF_WIM, rl, acc2);
        __syncthreads();                         // all WiM reads (ldsm + lds) done
        if (i < 127) {                           // prefetch WiM(i+1)
            const uint4* src = (const uint4*)(g_WiM + (size_t)(i + 1) * 16384);
            #pragma unroll
            for (int q = 0; q < 8; q++) {
                int v = (q << 8) + tid;
                cpa16(aWiM + (uint32_t)(v << 4), src + v);
            }
            asm volatile("cp.async.commit_group;");
        }
        // ---- E0 tensor: h1 = relu(pre + z*wz + bi) -> sHA/sHB (cols 0..111) ----
        #pragma unroll
        for (int t = 0; t < 2; t++) {
            float (*acc)[NT_T][4] = t ? accB : accA;
            const uint32_t hB = t ? aHB : aHA;
            const float* zt = zg + (t << 7);
            #pragma unroll
            for (int mt = 0; mt < 2; mt++) {
                int r0 = mrow + mt * 16 + gr0, r1 = r0 + 8;
                float z0 = zt[r0], z1 = zt[r1];
                uint32_t row0 = hB + (uint32_t)(r0 * 256), row1 = hB + (uint32_t)(r1 * 256);
                uint32_t xr = (uint32_t)((r0 & 7) << 4);
                #pragma unroll
                for (int nt = 0; nt < NT_T; nt++) {
                    int c = ncol + nt * 8 + gc0;
                    float2 a0 = sC0[c], a1 = sC0[c + 1];
                    float v00 = fmaxf(fmaf(z0, a0.x, acc[mt][nt][0]) + a0.y, 0.f);
                    float v01 = fmaxf(fmaf(z0, a1.x, acc[mt][nt][1]) + a1.y, 0.f);
                    float v10 = fmaxf(fmaf(z1, a0.x, acc[mt][nt][2]) + a0.y, 0.f);
                    float v11 = fmaxf(fmaf(z1, a1.x, acc[mt][nt][3]) + a1.y, 0.f);
                    uint32_t cb = ((uint32_t)(2 * c)) ^ xr;
                    *(__half2*)(sm + (row0 + cb - smBase)) = __floats2half2_rn(v00, v01);
                    *(__half2*)(sm + (row1 + cb - smBase)) = __floats2half2_rn(v10, v11);
                }
            }
        }
        // ---- E0 FMA: own row, cols 112..127 ----
        {
            char* hRow = sm + ownTileH + rl * 256;
            #pragma unroll
            for (int c = 0; c < 16; c += 2) {
                float2 a0 = sC0[112 + c], a1 = sC0[113 + c];
                float v0 = fmaxf(fmaf(zOwn, a0.x, __low2float(acc2[c]) + __high2float(acc2[c])) + a0.y, 0.f);
                float v1 = fmaxf(fmaf(zOwn, a1.x, __low2float(acc2[c + 1]) + __high2float(acc2[c + 1])) + a1.y, 0.f);
                *(__half2*)(hRow + (((uint32_t)(224 + 2 * c)) ^ xrOwn)) = __floats2half2_rn(v0, v1);
            }
        }
        __syncthreads();

        // ---- G1 ----
        gemm2x(aHA, aHB, aW1, lane, mrow, ncol, accA, accB);
        fma_cols(sm, ownTileH, OFF_W1, rl, acc2);
        __syncthreads();
        // ---- E1 tensor: h2 = relu(pre + b1) in place ----
        #pragma unroll
        for (int t = 0; t < 2; t++) {
            float (*acc)[NT_T][4] = t ? accB : accA;
            const uint32_t hB = t ? aHB : aHA;
            #pragma unroll
            for (int mt = 0; mt < 2; mt++) {
                int r0 = mrow + mt * 16 + gr0, r1 = r0 + 8;
                uint32_t row0 = hB + (uint32_t)(r0 * 256), row1 = hB + (uint32_t)(r1 * 256);
                uint32_t xr = (uint32_t)((r0 & 7) << 4);
                #pragma unroll
                for (int nt = 0; nt < NT_T; nt++) {
                    int c = ncol + nt * 8 + gc0;
                    float q0 = sB12[c].x, q1 = sB12[c + 1].x;
                    float v00 = fmaxf(acc[mt][nt][0] + q0, 0.f);
                    float v01 = fmaxf(acc[mt][nt][1] + q1, 0.f);
                    float v10 = fmaxf(acc[mt][nt][2] + q0, 0.f);
                    float v11 = fmaxf(acc[mt][nt][3] + q1, 0.f);
                    uint32_t cb = ((uint32_t)(2 * c)) ^ xr;
                    *(__half2*)(sm + (row0 + cb - smBase)) = __floats2half2_rn(v00, v01);
                    *(__half2*)(sm + (row1 + cb - smBase)) = __floats2half2_rn(v10, v11);
                }
            }
        }
        // ---- E1 FMA ----
        {
            char* hRow = sm + ownTileH + rl * 256;
            #pragma unroll
            for (int c = 0; c < 16; c += 2) {
                float v0 = fmaxf(__low2float(acc2[c]) + __high2float(acc2[c]) + sB12[112 + c].x, 0.f);
                float v1 = fmaxf(__low2float(acc2[c + 1]) + __high2float(acc2[c + 1]) + sB12[113 + c].x, 0.f);
                *(__half2*)(hRow + (((uint32_t)(224 + 2 * c)) ^ xrOwn)) = __floats2half2_rn(v0, v1);
            }
        }
        __syncthreads();

        // ---- G2 ----
        gemm2x(aHA, aHB, aW2, lane, mrow, ncol, accA, accB);
        fma_cols(sm, ownTileH, OFF_W2, rl, acc2);

        // FMA partial of fc_f dot over cols 112..127 (own row)
        float fmaPart = 0.f;
        #pragma unroll
        for (int c = 0; c < 16; c++) {
            float v = __low2float(acc2[c]) + __high2float(acc2[c]) + sB12[112 + c].y;
            fmaPart = fmaf(fmaxf(v, 0.f), sWf[112 + c], fmaPart);
        }

        // ---- E2: per-tile pass; o = relu(pre + b2) @ Wf + bf ----
        #pragma unroll
        for (int t = 0; t < 2; t++) {
            float (*acc)[NT_T][4] = t ? accB : accA;
            float p[2][2] = {{0.f, 0.f}, {0.f, 0.f}};
            #pragma unroll
            for (int mt = 0; mt < 2; mt++)
                #pragma unroll
                for (int nt = 0; nt < NT_T; nt++) {
                    int c = ncol + nt * 8 + gc0;
                    float wf0 = sWf[c], wf1 = sWf[c + 1];
                    float q0 = sB12[c].y, q1 = sB12[c + 1].y;
                    p[mt][0] = fmaf(fmaxf(acc[mt][nt][0] + q0, 0.f), wf0,
                               fmaf(fmaxf(acc[mt][nt][1] + q1, 0.f), wf1, p[mt][0]));
                    p[mt][1] = fmaf(fmaxf(acc[mt][nt][2] + q0, 0.f), wf0,
                               fmaf(fmaxf(acc[mt][nt][3] + q1, 0.f), wf1, p[mt][1]));
                }
            __syncthreads();                     // sO2 (alias sC0) free
            #pragma unroll
            for (int mt = 0; mt < 2; mt++)
                #pragma unroll
                for (int h = 0; h < 2; h++) {
                    float v = p[mt][h];
                    v += __shfl_xor_sync(0xffffffffu, v, 1);
                    v += __shfl_xor_sync(0xffffffffu, v, 2);
                    if ((lane & 3) == 0)
                        sO2[wn * 128 + mrow + mt * 16 + h * 8 + gr0] = v;
                }
            __syncthreads();
            if ((tid >> 7) == t) {
                float o = sO2[rl] + sO2[128 + rl] + fmaPart + bfi;
                out[(b0 + (size_t)(t << 7) + rl) * 128 + i] = o;
                char* base = sm + ((t) ? OFF_OUTB : OFF_OUTA);
                *(__half*)(base + tile_off(rl, i)) = __float2half(o);
            }
        }
        if (i < 127) asm volatile("cp.async.wait_group 0;");
        __syncthreads();
    }
}

// ---- host ----
extern "C" void kernel_launch(void* const* d_in, const int* in_sizes, int n_in,
                              void* d_out, int out_size) {
    const float* x  = (const float*)d_in[0];
    const float* z  = (const float*)d_in[1];
    const float* M  = (const float*)d_in[2];
    const float* Wi = (const float*)d_in[3];
    const float* bi = (const float*)d_in[4];
    const float* Wf = (const float*)d_in[5];
    const float* bf = (const float*)d_in[6];
    const float* W1 = (const float*)d_in[7];
    const float* b1 = (const float*)d_in[8];
    const float* W2 = (const float*)d_in[9];
    const float* b2 = (const float*)d_in[10];
    int Bn = in_sizes[0] / 128;

    cudaFuncSetAttribute(gen_main, cudaFuncAttributeMaxDynamicSharedMemorySize, SMEM_TOTAL);

    prep_weights<<<130, 256>>>(Wi, M, W1, W2);
    transpose_z<<<dim3(Bn / 32, 4), dim3(32, 8)>>>(z, Bn);
    gen_main<<<Bn / 256, 256, SMEM_TOTAL>>>(x, bi, Wf, bf, b1, b2, (float*)d_out, Bn);
}

// round 7
// speedup vs baseline: 1.8333x; 1.8333x over previous
#include <cuda_runtime.h>
#include <cuda_fp16.h>
#include <cstdint>

// ---- SMEM layout (bytes): 7 x 32KB unpadded swizzled fp16 tiles + small ----
#define OFF_OUTA 0
#define OFF_OUTB 32768
#define OFF_HA   65536
#define OFF_HB   98304
#define OFF_WIM  131072
#define OFF_W1   163840
#define OFF_W2   196608
#define OFF_C0   229376   // float2 (wz,bi)[128] = 1KB ; ALIASED as sO2 float[256]
#define OFF_WF   230400   // float[128]
#define OFF_B12  230912   // float2 (b1,b2)[128] = 1KB
#define SMEM_TOTAL 231936

// ---- device scratch ----
__device__ __half g_WiM[(size_t)128 * 16384];  // per-i swizzled 128x128 fp16 image
__device__ float  g_wz[128 * 128];
__device__ __half g_W1h[16384];                // swizzled image
__device__ __half g_W2h[16384];
__device__ float  g_zT[(size_t)128 * 131072];  // [i][b]

// XOR-swizzled byte offset in a 128x128 fp16 tile (row = 256B)
__host__ __device__ __forceinline__ uint32_t tile_off(int r, int c) {
    return (uint32_t)(r * 256 + ((c * 2) ^ ((r & 7) << 4)));
}

// ---- prologue kernels ----
__global__ void prep_weights(const float* __restrict__ Wi, const float* __restrict__ M,
                             const float* __restrict__ W1, const float* __restrict__ W2) {
    int i = blockIdx.x;
    if (i < 128) {
        const float* Wii = Wi + (size_t)i * 16512;   // 128*129
        for (int v = threadIdx.x; v < 16384; v += blockDim.x) {
            int j = v >> 7, k = v & 127;
            float m = (k == i) ? 0.f : M[k * 128 + i];
            g_WiM[(size_t)i * 16384 + (tile_off(j, k) >> 1)] = __float2half(Wii[j * 129 + k] * m);
        }
        for (int j = threadIdx.x; j < 128; j += blockDim.x)
            g_wz[i * 128 + j] = Wii[j * 129 + 128];
    } else if (i == 128) {
        for (int v = threadIdx.x; v < 16384; v += blockDim.x)
            g_W1h[tile_off(v >> 7, v & 127) >> 1] = __float2half(W1[v]);
    } else {
        for (int v = threadIdx.x; v < 16384; v += blockDim.x)
            g_W2h[tile_off(v >> 7, v & 127) >> 1] = __float2half(W2[v]);
    }
}

__global__ void transpose_z(const float* __restrict__ z, int Bn) {
    __shared__ float t[32][33];
    int b0 = blockIdx.x * 32, i0 = blockIdx.y * 32;
    #pragma unroll
    for (int r = threadIdx.y; r < 32; r += 8)
        t[r][threadIdx.x] = z[(size_t)(b0 + r) * 128 + i0 + threadIdx.x];
    __syncthreads();
    #pragma unroll
    for (int r = threadIdx.y; r < 32; r += 8)
        g_zT[(size_t)(i0 + r) * Bn + b0 + threadIdx.x] = t[threadIdx.x][r];
}

// ---- mma helpers ----
__device__ __forceinline__ void ldsm4(uint32_t addr, uint32_t* r) {
    asm volatile("ldmatrix.sync.aligned.m8n8.x4.shared.b16 {%0,%1,%2,%3},[%4];"
        : "=r"(r[0]), "=r"(r[1]), "=r"(r[2]), "=r"(r[3]) : "r"(addr));
}
__device__ __forceinline__ void mma16816(float* c, const uint32_t* a, const uint32_t* b) {
    asm volatile("mma.sync.aligned.m16n8k16.row.col.f32.f16.f16.f32 "
        "{%0,%1,%2,%3},{%4,%5,%6,%7},{%8,%9},{%0,%1,%2,%3};"
        : "+f"(c[0]), "+f"(c[1]), "+f"(c[2]), "+f"(c[3])
        : "r"(a[0]), "r"(a[1]), "r"(a[2]), "r"(a[3]), "r"(b[0]), "r"(b[1]));
}
__device__ __forceinline__ void cpa16(uint32_t s, const void* g) {
    asm volatile("cp.async.cg.shared.global [%0],[%1],16;" :: "r"(s), "l"(g));
}

// NT-tile GEMM: C{a[,b]}[128,128] = A{a[,b]}[128,k] * B[n,k]^T ; B loaded once/kstep
template<int NT>
__device__ __forceinline__ void gemmNx(uint32_t aBaseA, uint32_t aBaseB, uint32_t bBase,
                                       int lane, int mrow, int ncol,
                                       float accA[2][8][4], float accB[2][8][4]) {
    #pragma unroll
    for (int mt = 0; mt < 2; mt++)
        #pragma unroll
        for (int nt = 0; nt < 8; nt++)
            #pragma unroll
            for (int c = 0; c < 4; c++) {
                accA[mt][nt][c] = 0.f;
                if (NT == 2) accB[mt][nt][c] = 0.f;
            }

    const int rA = mrow + (lane & 15);
    const uint32_t rowA0 = aBaseA + (uint32_t)(rA * 256);
    const uint32_t rowB0 = aBaseB + (uint32_t)(rA * 256);
    const uint32_t xorA = (uint32_t)((rA & 7) << 4);
    const uint32_t cA = (lane & 16) ? 16u : 0u;
    const int rB = ncol + (lane & 7) + ((lane & 16) ? 8 : 0);
    const uint32_t rowW = bBase + (uint32_t)(rB * 256);
    const uint32_t xorB = (uint32_t)((lane & 7) << 4);
    const uint32_t cB = (lane & 8) ? 16u : 0u;

    #pragma unroll
    for (int ks = 0; ks < 8; ks++) {
        uint32_t offA = ((uint32_t)(ks * 32) + cA) ^ xorA;
        uint32_t offB = ((uint32_t)(ks * 32) + cB) ^ xorB;
        uint32_t a0[4], a1[4], c0[4], c1[4], b[16];
        ldsm4(rowA0 + offA, a0);
        ldsm4(rowA0 + 4096 + offA, a1);
        if (NT == 2) {
            ldsm4(rowB0 + offA, c0);
            ldsm4(rowB0 + 4096 + offA, c1);
        }
        #pragma unroll
        for (int q = 0; q < 4; q++) ldsm4(rowW + (uint32_t)(q * 4096) + offB, b + 4 * q);
        #pragma unroll
        for (int nt = 0; nt < 8; nt++) {
            const uint32_t* bb = b + (nt >> 1) * 4 + (nt & 1) * 2;
            mma16816(accA[0][nt], a0, bb);
            mma16816(accA[1][nt], a1, bb);
            if (NT == 2) {
                mma16816(accB[0][nt], c0, bb);
                mma16816(accB[1][nt], c1, bb);
            }
        }
    }
}

// ---- main kernel: 1 CTA = NT batch tiles of 128, legacy-HMMA ----
template<int NT>
__global__ __launch_bounds__(256, 1)
void gen_main(const float* __restrict__ x,  const float* __restrict__ bi,
              const float* __restrict__ Wf, const float* __restrict__ bf,
              const float* __restrict__ b1, const float* __restrict__ b2,
              float* __restrict__ out, int Bn, int baseRow)
{
    extern __shared__ char sm[];
    const int tid = threadIdx.x, lane = tid & 31, wid = tid >> 5;
    const int wm = wid >> 1, wn = wid & 1;
    const int mrow = wm * 32, ncol = wn * 64;
    const int gr0 = lane >> 2, gc0 = 2 * (lane & 3);
    const size_t b0 = (size_t)baseRow + (size_t)blockIdx.x * (128 * NT);

    const uint32_t smBase = (uint32_t)__cvta_generic_to_shared(sm);
    const uint32_t aOutA = smBase + OFF_OUTA, aOutB = smBase + OFF_OUTB;
    const uint32_t aHA = smBase + OFF_HA, aHB = smBase + OFF_HB;
    const uint32_t aWiM = smBase + OFF_WIM, aW1 = smBase + OFF_W1, aW2 = smBase + OFF_W2;
    float2* sC0  = (float2*)(sm + OFF_C0);
    float*  sO2  = (float*)(sm + OFF_C0);      // alias; disjoint lifetime within step
    float*  sWf  = (float*)(sm + OFF_WF);
    float2* sB12 = (float2*)(sm + OFF_B12);

    // ---- stage x into tiles (fp16, swizzled) ----
    const float4* xg = (const float4*)(x + b0 * 128);
    #pragma unroll
    for (int q = 0; q < 16 * NT; q++) {
        int v = (q << 8) + tid;
        float4 f = xg[v];
        int rv = v >> 5, c4 = (v & 31) << 2;
        uint32_t off = tile_off(rv & 127, c4);
        char* base = sm + ((rv >> 7) ? OFF_OUTB : OFF_OUTA);
        *(__half2*)(base + off)     = __floats2half2_rn(f.x, f.y);
        *(__half2*)(base + off + 4) = __floats2half2_rn(f.z, f.w);
    }
    // ---- stage W1/W2 (pre-swizzled) + WiM(0) ----
    #pragma unroll
    for (int q = 0; q < 8; q++) {
        int v = (q << 8) + tid;
        ((uint4*)(sm + OFF_W1))[v] = ((const uint4*)g_W1h)[v];
        ((uint4*)(sm + OFF_W2))[v] = ((const uint4*)g_W2h)[v];
        cpa16(aWiM + (uint32_t)(v << 4), ((const uint4*)g_WiM) + v);
    }
    asm volatile("cp.async.commit_group;");
    if (tid < 128) sB12[tid] = make_float2(b1[tid], b2[tid]);
    asm volatile("cp.async.wait_group 0;");
    __syncthreads();

    float accA[2][8][4], accB[2][8][4];

    for (int i = 0; i < 128; i++) {
        if (tid < 128) {
            sC0[tid] = make_float2(g_wz[(i << 7) + tid], bi[(i << 7) + tid]);
            sWf[tid] = Wf[(i << 7) + tid];
        }
        const float bfi = bf[i];
        const float* zg = g_zT + (size_t)i * Bn + b0;
        __syncthreads();

        // ---- G0: h1_pre = out @ WiM^T ----
        gemmNx<NT>(aOutA, aOutB, aWiM, lane, mrow, ncol, accA, accB);
        __syncthreads();                         // all WiM reads done
        if (i < 127) {                           // prefetch WiM(i+1)
            const uint4* src = (const uint4*)(g_WiM + (size_t)(i + 1) * 16384);
            #pragma unroll
            for (int q = 0; q < 8; q++) {
                int v = (q << 8) + tid;
                cpa16(aWiM + (uint32_t)(v << 4), src + v);
            }
            asm volatile("cp.async.commit_group;");
        }
        // ---- E0: h1 = relu(pre + z*wz + bi) -> sHA/sHB ----
        #pragma unroll
        for (int t = 0; t < NT; t++) {
            float (*acc)[8][4] = t ? accB : accA;
            const uint32_t hB = t ? aHB : aHA;
            const float* zt = zg + (t << 7);
            #pragma unroll
            for (int mt = 0; mt < 2; mt++) {
                int r0 = mrow + mt * 16 + gr0, r1 = r0 + 8;
                float z0 = zt[r0], z1 = zt[r1];
                uint32_t row0 = hB + (uint32_t)(r0 * 256), row1 = hB + (uint32_t)(r1 * 256);
                uint32_t xr = (uint32_t)((r0 & 7) << 4);
                #pragma unroll
                for (int nt = 0; nt < 8; nt++) {
                    int c = ncol + nt * 8 + gc0;
                    float2 a0 = sC0[c], a1 = sC0[c + 1];
                    float v00 = fmaxf(fmaf(z0, a0.x, acc[mt][nt][0]) + a0.y, 0.f);
                    float v01 = fmaxf(fmaf(z0, a1.x, acc[mt][nt][1]) + a1.y, 0.f);
                    float v10 = fmaxf(fmaf(z1, a0.x, acc[mt][nt][2]) + a0.y, 0.f);
                    float v11 = fmaxf(fmaf(z1, a1.x, acc[mt][nt][3]) + a1.y, 0.f);
                    uint32_t cb = ((uint32_t)(2 * c)) ^ xr;
                    *(__half2*)(sm + (row0 + cb - smBase)) = __floats2half2_rn(v00, v01);
                    *(__half2*)(sm + (row1 + cb - smBase)) = __floats2half2_rn(v10, v11);
                }
            }
        }
        __syncthreads();

        // ---- G1: h2_pre = h1 @ W1^T ----
        gemmNx<NT>(aHA, aHB, aW1, lane, mrow, ncol, accA, accB);
        __syncthreads();
        // ---- E1: h2 = relu(pre + b1) in place ----
        #pragma unroll
        for (int t = 0; t < NT; t++) {
            float (*acc)[8][4] = t ? accB : accA;
            const uint32_t hB = t ? aHB : aHA;
            #pragma unroll
            for (int mt = 0; mt < 2; mt++) {
                int r0 = mrow + mt * 16 + gr0, r1 = r0 + 8;
                uint32_t row0 = hB + (uint32_t)(r0 * 256), row1 = hB + (uint32_t)(r1 * 256);
                uint32_t xr = (uint32_t)((r0 & 7) << 4);
                #pragma unroll
                for (int nt = 0; nt < 8; nt++) {
                    int c = ncol + nt * 8 + gc0;
                    float q0 = sB12[c].x, q1 = sB12[c + 1].x;
                    float v00 = fmaxf(acc[mt][nt][0] + q0, 0.f);
                    float v01 = fmaxf(acc[mt][nt][1] + q1, 0.f);
                    float v10 = fmaxf(acc[mt][nt][2] + q0, 0.f);
                    float v11 = fmaxf(acc[mt][nt][3] + q1, 0.f);
                    uint32_t cb = ((uint32_t)(2 * c)) ^ xr;
                    *(__half2*)(sm + (row0 + cb - smBase)) = __floats2half2_rn(v00, v01);
                    *(__half2*)(sm + (row1 + cb - smBase)) = __floats2half2_rn(v10, v11);
                }
            }
        }
        __syncthreads();

        // ---- G2: h3_pre = h2 @ W2^T ----
        gemmNx<NT>(aHA, aHB, aW2, lane, mrow, ncol, accA, accB);

        // ---- E2: o = relu(pre + b2) @ Wf + bf ; write col i ----
        #pragma unroll
        for (int t = 0; t < NT; t++) {
            float (*acc)[8][4] = t ? accB : accA;
            float p[2][2] = {{0.f, 0.f}, {0.f, 0.f}};
            #pragma unroll
            for (int mt = 0; mt < 2; mt++)
                #pragma unroll
                for (int nt = 0; nt < 8; nt++) {
                    int c = ncol + nt * 8 + gc0;
                    float wf0 = sWf[c], wf1 = sWf[c + 1];
                    float q0 = sB12[c].y, q1 = sB12[c + 1].y;
                    p[mt][0] = fmaf(fmaxf(acc[mt][nt][0] + q0, 0.f), wf0,
                               fmaf(fmaxf(acc[mt][nt][1] + q1, 0.f), wf1, p[mt][0]));
                    p[mt][1] = fmaf(fmaxf(acc[mt][nt][2] + q0, 0.f), wf0,
                               fmaf(fmaxf(acc[mt][nt][3] + q1, 0.f), wf1, p[mt][1]));
                }
            __syncthreads();                     // sO2 free (prev use done)
            #pragma unroll
            for (int mt = 0; mt < 2; mt++)
                #pragma unroll
                for (int h = 0; h < 2; h++) {
                    float v = p[mt][h];
                    v += __shfl_xor_sync(0xffffffffu, v, 1);
                    v += __shfl_xor_sync(0xffffffffu, v, 2);
                    if ((lane & 3) == 0)
                        sO2[wn * 128 + mrow + mt * 16 + h * 8 + gr0] = v;
                }
            __syncthreads();
            if (tid < 128) {
                float o = sO2[tid] + sO2[128 + tid] + bfi;
                out[(b0 + (size_t)(t << 7) + tid) * 128 + i] = o;
                char* base = sm + (t ? OFF_OUTB : OFF_OUTA);
                *(__half*)(base + tile_off(tid, i)) = __float2half(o);
            }
        }
        if (i < 127) asm volatile("cp.async.wait_group 0;");
        __syncthreads();
    }
}

// ---- host ----
extern "C" void kernel_launch(void* const* d_in, const int* in_sizes, int n_in,
                              void* d_out, int out_size) {
    const float* x  = (const float*)d_in[0];
    const float* z  = (const float*)d_in[1];
    const float* M  = (const float*)d_in[2];
    const float* Wi = (const float*)d_in[3];
    const float* bi = (const float*)d_in[4];
    const float* Wf = (const float*)d_in[5];
    const float* bf = (const float*)d_in[6];
    const float* W1 = (const float*)d_in[7];
    const float* b1 = (const float*)d_in[8];
    const float* W2 = (const float*)d_in[9];
    const float* b2 = (const float*)d_in[10];
    int Bn = in_sizes[0] / 128;

    cudaFuncSetAttribute(gen_main<2>, cudaFuncAttributeMaxDynamicSharedMemorySize, SMEM_TOTAL);
    cudaFuncSetAttribute(gen_main<1>, cudaFuncAttributeMaxDynamicSharedMemorySize, SMEM_TOTAL);

    prep_weights<<<130, 256>>>(Wi, M, W1, W2);
    transpose_z<<<dim3(Bn / 32, 4), dim3(32, 8)>>>(z, Bn);

    // Mixed grid to kill wave quantization on 148 SMs:
    // pair-CTAs in full waves of 148, remainder as single-tile CTAs (1 wave).
    int tiles = Bn / 128;                       // 1024
    int nPair = ((tiles / 2) / 148) * 148;      // 444
    int nSingle = tiles - 2 * nPair;            // 136
    if (nPair > 0)
        gen_main<2><<<nPair, 256, SMEM_TOTAL>>>(x, bi, Wf, bf, b1, b2, (float*)d_out, Bn, 0);
    if (nSingle > 0)
        gen_main<1><<<nSingle, 256, SMEM_TOTAL>>>(x, bi, Wf, bf, b1, b2, (float*)d_out, Bn, nPair * 256);
}

// round 8
// speedup vs baseline: 2.1068x; 1.1491x over previous
#include <cuda_runtime.h>
#include <cuda_fp16.h>
#include <cstdint>

// ---- SMEM layout (bytes): 7 x 32KB unpadded swizzled fp16 tiles + small ----
#define OFF_OUTA 0
#define OFF_OUTB 32768
#define OFF_HA   65536
#define OFF_HB   98304
#define OFF_WIM  131072
#define OFF_W1   163840
#define OFF_W2   196608
#define OFF_C0   229376   // float2 (wz,bi)[128] = 1KB ; ALIASED as sO2 float[256]
#define OFF_WF   230400   // float[128]
#define OFF_B12  230912   // float2 (b1,b2)[128] = 1KB
#define SMEM_TOTAL 231936

// ---- device scratch ----
__device__ __half g_WiM[(size_t)128 * 16384];  // per-i swizzled 128x128 fp16 image
__device__ float  g_wz[128 * 128];
__device__ __half g_W1h[16384];                // swizzled image
__device__ __half g_W2h[16384];
__device__ float  g_zT[(size_t)128 * 131072];  // [i][b]

// XOR-swizzled byte offset in a 128x128 fp16 tile (row = 256B)
__host__ __device__ __forceinline__ uint32_t tile_off(int r, int c) {
    return (uint32_t)(r * 256 + ((c * 2) ^ ((r & 7) << 4)));
}

// ---- prologue kernels ----
__global__ void prep_weights(const float* __restrict__ Wi, const float* __restrict__ M,
                             const float* __restrict__ W1, const float* __restrict__ W2) {
    int i = blockIdx.x;
    if (i < 128) {
        const float* Wii = Wi + (size_t)i * 16512;   // 128*129
        for (int v = threadIdx.x; v < 16384; v += blockDim.x) {
            int j = v >> 7, k = v & 127;
            float m = (k == i) ? 0.f : M[k * 128 + i];
            g_WiM[(size_t)i * 16384 + (tile_off(j, k) >> 1)] = __float2half(Wii[j * 129 + k] * m);
        }
        for (int j = threadIdx.x; j < 128; j += blockDim.x)
            g_wz[i * 128 + j] = Wii[j * 129 + 128];
    } else if (i == 128) {
        for (int v = threadIdx.x; v < 16384; v += blockDim.x)
            g_W1h[tile_off(v >> 7, v & 127) >> 1] = __float2half(W1[v]);
    } else {
        for (int v = threadIdx.x; v < 16384; v += blockDim.x)
            g_W2h[tile_off(v >> 7, v & 127) >> 1] = __float2half(W2[v]);
    }
}

__global__ void transpose_z(const float* __restrict__ z, int Bn) {
    __shared__ float t[32][33];
    int b0 = blockIdx.x * 32, i0 = blockIdx.y * 32;
    #pragma unroll
    for (int r = threadIdx.y; r < 32; r += 8)
        t[r][threadIdx.x] = z[(size_t)(b0 + r) * 128 + i0 + threadIdx.x];
    __syncthreads();
    #pragma unroll
    for (int r = threadIdx.y; r < 32; r += 8)
        g_zT[(size_t)(i0 + r) * Bn + b0 + threadIdx.x] = t[threadIdx.x][r];
}

// ---- mma helpers ----
__device__ __forceinline__ void ldsm4(uint32_t addr, uint32_t* r) {
    asm volatile("ldmatrix.sync.aligned.m8n8.x4.shared.b16 {%0,%1,%2,%3},[%4];"
        : "=r"(r[0]), "=r"(r[1]), "=r"(r[2]), "=r"(r[3]) : "r"(addr));
}
__device__ __forceinline__ void mma16816(float* c, const uint32_t* a, const uint32_t* b) {
    asm volatile("mma.sync.aligned.m16n8k16.row.col.f32.f16.f16.f32 "
        "{%0,%1,%2,%3},{%4,%5,%6,%7},{%8,%9},{%0,%1,%2,%3};"
        : "+f"(c[0]), "+f"(c[1]), "+f"(c[2]), "+f"(c[3])
        : "r"(a[0]), "r"(a[1]), "r"(a[2]), "r"(a[3]), "r"(b[0]), "r"(b[1]));
}
__device__ __forceinline__ void cpa16(uint32_t s, const void* g) {
    asm volatile("cp.async.cg.shared.global [%0],[%1],16;" :: "r"(s), "l"(g));
}

// ================= interleaved gemm + epilogue-chunk engine =================
// Computes accG = A(aBase) @ W(bBase)^T for ONE tile while, per k-step, applying
// the epilogue chunk nt=ks for the OTHER tile (acc accE).
// EPI: 0 none | 1 relu(accE + z*wz + bi)->H | 2 relu(accE + b1)->H | 3 fc_f dot->p
template<int EPI>
__device__ __forceinline__ void gemm_ileave(
    uint32_t aBase, uint32_t bBase,
    float accG[2][8][4], const float accE[2][8][4],
    char* hEpi,                       // epi H tile base pointer (EPI 1,2)
    const float2* sC0, const float2* sB12, const float* sWf,
    float z0, float z1, float z2, float z3,
    float p[2][2],
    int lane, int mrow, int ncol)
{
    #pragma unroll
    for (int mt = 0; mt < 2; mt++)
        #pragma unroll
        for (int nt = 0; nt < 8; nt++)
            #pragma unroll
            for (int c = 0; c < 4; c++) accG[mt][nt][c] = 0.f;

    const int gr0 = lane >> 2, gc0 = 2 * (lane & 3);
    const int rA = mrow + (lane & 15);
    const uint32_t rowA0 = aBase + (uint32_t)(rA * 256);
    const uint32_t xorA = (uint32_t)((rA & 7) << 4);
    const uint32_t cA = (lane & 16) ? 16u : 0u;
    const int rB = ncol + (lane & 7) + ((lane & 16) ? 8 : 0);
    const uint32_t rowW = bBase + (uint32_t)(rB * 256);
    const uint32_t xorB = (uint32_t)((lane & 7) << 4);
    const uint32_t cB = (lane & 8) ? 16u : 0u;
    const uint32_t xrE = (uint32_t)(gr0 << 4);   // epi rows all have (r&7)==gr0

    #pragma unroll
    for (int ks = 0; ks < 8; ks++) {
        uint32_t offA = ((uint32_t)(ks * 32) + cA) ^ xorA;
        uint32_t offB = ((uint32_t)(ks * 32) + cB) ^ xorB;
        uint32_t a0[4], a1[4], b[16];
        ldsm4(rowA0 + offA, a0);
        ldsm4(rowA0 + 4096 + offA, a1);
        #pragma unroll
        for (int q = 0; q < 4; q++) ldsm4(rowW + (uint32_t)(q * 4096) + offB, b + 4 * q);
        #pragma unroll
        for (int nt = 0; nt < 8; nt++) {
            const uint32_t* bb = b + (nt >> 1) * 4 + (nt & 1) * 2;
            mma16816(accG[0][nt], a0, bb);
            mma16816(accG[1][nt], a1, bb);
        }
        // ---- epilogue chunk (other tile), nt = ks ----
        if (EPI == 1 || EPI == 2) {
            const int nt = ks;
            const int c = ncol + nt * 8 + gc0;
            float x0, x1, za0 = 0.f, za1 = 0.f;
            if (EPI == 1) { float2 t0 = sC0[c], t1 = sC0[c + 1];
                            x0 = t0.y; x1 = t1.y; za0 = t0.x; za1 = t1.x; }
            else          { x0 = sB12[c].x; x1 = sB12[c + 1].x; }
            const uint32_t cb = ((uint32_t)(2 * c)) ^ xrE;
            #pragma unroll
            for (int mt = 0; mt < 2; mt++) {
                const int r0 = mrow + mt * 16 + gr0, r1 = r0 + 8;
                const float zlo = mt ? z2 : z0, zhi = mt ? z3 : z1;
                float v00 = accE[mt][nt][0], v01 = accE[mt][nt][1];
                float v10 = accE[mt][nt][2], v11 = accE[mt][nt][3];
                if (EPI == 1) {
                    v00 = fmaf(zlo, za0, v00); v01 = fmaf(zlo, za1, v01);
                    v10 = fmaf(zhi, za0, v10); v11 = fmaf(zhi, za1, v11);
                }
                v00 = fmaxf(v00 + x0, 0.f); v01 = fmaxf(v01 + x1, 0.f);
                v10 = fmaxf(v10 + x0, 0.f); v11 = fmaxf(v11 + x1, 0.f);
                *(__half2*)(hEpi + r0 * 256 + cb) = __floats2half2_rn(v00, v01);
                *(__half2*)(hEpi + r1 * 256 + cb) = __floats2half2_rn(v10, v11);
            }
        }
        if (EPI == 3) {
            const int nt = ks;
            const int c = ncol + nt * 8 + gc0;
            const float wf0 = sWf[c], wf1 = sWf[c + 1];
            const float q0 = sB12[c].y, q1 = sB12[c + 1].y;
            #pragma unroll
            for (int mt = 0; mt < 2; mt++) {
                p[mt][0] = fmaf(fmaxf(accE[mt][nt][0] + q0, 0.f), wf0,
                           fmaf(fmaxf(accE[mt][nt][1] + q1, 0.f), wf1, p[mt][0]));
                p[mt][1] = fmaf(fmaxf(accE[mt][nt][2] + q0, 0.f), wf0,
                           fmaf(fmaxf(accE[mt][nt][3] + q1, 0.f), wf1, p[mt][1]));
            }
        }
    }
}

// ---- pair kernel: 1 CTA = 2 tiles, epilogue-interleaved phases ----
__global__ __launch_bounds__(256, 1)
void gen_pair(const float* __restrict__ x,  const float* __restrict__ bi,
              const float* __restrict__ Wf, const float* __restrict__ bf,
              const float* __restrict__ b1, const float* __restrict__ b2,
              float* __restrict__ out, int Bn, int baseRow)
{
    extern __shared__ char sm[];
    const int tid = threadIdx.x, lane = tid & 31, wid = tid >> 5;
    const int wm = wid >> 1, wn = wid & 1;
    const int mrow = wm * 32, ncol = wn * 64;
    const int gr0 = lane >> 2;
    const size_t b0 = (size_t)baseRow + (size_t)blockIdx.x * 256;

    const uint32_t smBase = (uint32_t)__cvta_generic_to_shared(sm);
    const uint32_t aOutA = smBase + OFF_OUTA, aOutB = smBase + OFF_OUTB;
    const uint32_t aHA = smBase + OFF_HA, aHB = smBase + OFF_HB;
    const uint32_t aWiM = smBase + OFF_WIM, aW1 = smBase + OFF_W1, aW2 = smBase + OFF_W2;
    char* hA = sm + OFF_HA; char* hB = sm + OFF_HB;
    float2* sC0  = (float2*)(sm + OFF_C0);
    float*  sO2  = (float*)(sm + OFF_C0);      // alias; disjoint lifetimes
    float*  sWf  = (float*)(sm + OFF_WF);
    float2* sB12 = (float2*)(sm + OFF_B12);

    // ---- stage x into both tiles ----
    const float4* xg = (const float4*)(x + b0 * 128);
    #pragma unroll
    for (int q = 0; q < 32; q++) {
        int v = (q << 8) + tid;
        float4 f = xg[v];
        int rv = v >> 5, c4 = (v & 31) << 2;
        uint32_t off = tile_off(rv & 127, c4);
        char* base = sm + ((rv >> 7) ? OFF_OUTB : OFF_OUTA);
        *(__half2*)(base + off)     = __floats2half2_rn(f.x, f.y);
        *(__half2*)(base + off + 4) = __floats2half2_rn(f.z, f.w);
    }
    #pragma unroll
    for (int q = 0; q < 8; q++) {
        int v = (q << 8) + tid;
        ((uint4*)(sm + OFF_W1))[v] = ((const uint4*)g_W1h)[v];
        ((uint4*)(sm + OFF_W2))[v] = ((const uint4*)g_W2h)[v];
        cpa16(aWiM + (uint32_t)(v << 4), ((const uint4*)g_WiM) + v);
    }
    asm volatile("cp.async.commit_group;");
    if (tid < 128) sB12[tid] = make_float2(b1[tid], b2[tid]);
    asm volatile("cp.async.wait_group 0;");
    __syncthreads();

    float accA[2][8][4], accB[2][8][4];
    float pdum[2][2];

    for (int i = 0; i < 128; i++) {
        if (tid < 128) {
            sC0[tid] = make_float2(g_wz[(i << 7) + tid], bi[(i << 7) + tid]);
            sWf[tid] = Wf[(i << 7) + tid];
        }
        const float bfi = bf[i];
        const float* zg = g_zT + (size_t)i * Bn + b0;
        const int zr = mrow + gr0;
        float zA0 = zg[zr], zA1 = zg[zr + 8], zA2 = zg[zr + 16], zA3 = zg[zr + 24];
        float zB0 = zg[128 + zr], zB1 = zg[136 + zr], zB2 = zg[144 + zr], zB3 = zg[152 + zr];

        // P0: G0a (pure mma)
        gemm_ileave<0>(aOutA, aWiM, accA, accA, hA, sC0, sB12, sWf,
                       0.f, 0.f, 0.f, 0.f, pdum, lane, mrow, ncol);
        __syncthreads();                                   // S1: staging visible

        // P1: G0b + E0a -> H_a
        gemm_ileave<1>(aOutB, aWiM, accB, accA, hA, sC0, sB12, sWf,
                       zA0, zA1, zA2, zA3, pdum, lane, mrow, ncol);
        __syncthreads();                                   // S2: WiM reads done; H_a ready

        if (i < 127) {                                     // prefetch WiM(i+1)
            const uint4* src = (const uint4*)(g_WiM + (size_t)(i + 1) * 16384);
            #pragma unroll
            for (int q = 0; q < 8; q++) {
                int v = (q << 8) + tid;
                cpa16(aWiM + (uint32_t)(v << 4), src + v);
            }
            asm volatile("cp.async.commit_group;");
        }

        // P2: G1a (reads H_a) + E0b -> H_b
        gemm_ileave<1>(aHA, aW1, accA, accB, hB, sC0, sB12, sWf,
                       zB0, zB1, zB2, zB3, pdum, lane, mrow, ncol);
        __syncthreads();                                   // S3: H_b ready

        // P3: G1b (reads H_b) + E1a -> H_a (h2_a)
        gemm_ileave<2>(aHB, aW1, accB, accA, hA, sC0, sB12, sWf,
                       0.f, 0.f, 0.f, 0.f, pdum, lane, mrow, ncol);
        __syncthreads();                                   // S4

        // P4: G2a (reads H_a) + E1b -> H_b (h2_b)
        gemm_ileave<2>(aHA, aW2, accA, accB, hB, sC0, sB12, sWf,
                       0.f, 0.f, 0.f, 0.f, pdum, lane, mrow, ncol);
        __syncthreads();                                   // S5

        // P5: G2b (reads H_b) + E2a dot (consumes accA)
        float pA[2][2] = {{0.f, 0.f}, {0.f, 0.f}};
        gemm_ileave<3>(aHB, aW2, accB, accA, hA, sC0, sB12, sWf,
                       0.f, 0.f, 0.f, 0.f, pA, lane, mrow, ncol);
        #pragma unroll
        for (int mt = 0; mt < 2; mt++)
            #pragma unroll
            for (int h = 0; h < 2; h++) {
                float v = pA[mt][h];
                v += __shfl_xor_sync(0xffffffffu, v, 1);
                v += __shfl_xor_sync(0xffffffffu, v, 2);
                if ((lane & 3) == 0)
                    sO2[wn * 128 + mrow + mt * 16 + h * 8 + gr0] = v;  // tile-a partials
            }
        __syncthreads();                                   // S6: sO2a ready

        // P6: tile-a finalize + E2b dot
        float pB[2][2] = {{0.f, 0.f}, {0.f, 0.f}};
        #pragma unroll
        for (int nt = 0; nt < 8; nt++) {
            const int c = ncol + nt * 8 + 2 * (lane & 3);
            const float wf0 = sWf[c], wf1 = sWf[c + 1];
            const float q0 = sB12[c].y, q1 = sB12[c + 1].y;
            #pragma unroll
            for (int mt = 0; mt < 2; mt++) {
                pB[mt][0] = fmaf(fmaxf(accB[mt][nt][0] + q0, 0.f), wf0,
                            fmaf(fmaxf(accB[mt][nt][1] + q1, 0.f), wf1, pB[mt][0]));
                pB[mt][1] = fmaf(fmaxf(accB[mt][nt][2] + q0, 0.f), wf0,
                            fmaf(fmaxf(accB[mt][nt][3] + q1, 0.f), wf1, pB[mt][1]));
            }
        }
        if (tid < 128) {
            float o = sO2[tid] + sO2[128 + tid] + bfi;
            out[(b0 + tid) * 128 + i] = o;
            *(__half*)(sm + OFF_OUTA + tile_off(tid, i)) = __float2half(o);
        }
        __syncthreads();                                   // S7: sO2a reads done
        #pragma unroll
        for (int mt = 0; mt < 2; mt++)
            #pragma unroll
            for (int h = 0; h < 2; h++) {
                float v = pB[mt][h];
                v += __shfl_xor_sync(0xffffffffu, v, 1);
                v += __shfl_xor_sync(0xffffffffu, v, 2);
                if ((lane & 3) == 0)
                    sO2[wn * 128 + mrow + mt * 16 + h * 8 + gr0] = v;  // tile-b partials
            }
        if (i < 127) asm volatile("cp.async.wait_group 0;");
        __syncthreads();                                   // S8: sO2b + WiM ready
        if (tid < 128) {
            float o = sO2[tid] + sO2[128 + tid] + bfi;
            out[(b0 + 128 + tid) * 128 + i] = o;
            *(__half*)(sm + OFF_OUTB + tile_off(tid, i)) = __float2half(o);
        }
        __syncthreads();                                   // S9: OUT_b / sO2 settled
    }
}

// ---- single-tile kernel (leftover wave), non-interleaved (R7 NT=1) ----
__global__ __launch_bounds__(256, 1)
void gen_single(const float* __restrict__ x,  const float* __restrict__ bi,
                const float* __restrict__ Wf, const float* __restrict__ bf,
                const float* __restrict__ b1, const float* __restrict__ b2,
                float* __restrict__ out, int Bn, int baseRow)
{
    extern __shared__ char sm[];
    const int tid = threadIdx.x, lane = tid & 31, wid = tid >> 5;
    const int wm = wid >> 1, wn = wid & 1;
    const int mrow = wm * 32, ncol = wn * 64;
    const int gr0 = lane >> 2, gc0 = 2 * (lane & 3);
    const size_t b0 = (size_t)baseRow + (size_t)blockIdx.x * 128;

    const uint32_t smBase = (uint32_t)__cvta_generic_to_shared(sm);
    const uint32_t aOutA = smBase + OFF_OUTA;
    const uint32_t aHA = smBase + OFF_HA;
    const uint32_t aWiM = smBase + OFF_WIM, aW1 = smBase + OFF_W1, aW2 = smBase + OFF_W2;
    char* hA = sm + OFF_HA;
    float2* sC0  = (float2*)(sm + OFF_C0);
    float*  sO2  = (float*)(sm + OFF_C0);
    float*  sWf  = (float*)(sm + OFF_WF);
    float2* sB12 = (float2*)(sm + OFF_B12);

    const float4* xg = (const float4*)(x + b0 * 128);
    #pragma unroll
    for (int q = 0; q < 16; q++) {
        int v = (q << 8) + tid;
        float4 f = xg[v];
        int rv = v >> 5, c4 = (v & 31) << 2;
        uint32_t off = tile_off(rv & 127, c4);
        *(__half2*)(sm + OFF_OUTA + off)     = __floats2half2_rn(f.x, f.y);
        *(__half2*)(sm + OFF_OUTA + off + 4) = __floats2half2_rn(f.z, f.w);
    }
    #pragma unroll
    for (int q = 0; q < 8; q++) {
        int v = (q << 8) + tid;
        ((uint4*)(sm + OFF_W1))[v] = ((const uint4*)g_W1h)[v];
        ((uint4*)(sm + OFF_W2))[v] = ((const uint4*)g_W2h)[v];
        cpa16(aWiM + (uint32_t)(v << 4), ((const uint4*)g_WiM) + v);
    }
    asm volatile("cp.async.commit_group;");
    if (tid < 128) sB12[tid] = make_float2(b1[tid], b2[tid]);
    asm volatile("cp.async.wait_group 0;");
    __syncthreads();

    float accA[2][8][4];
    float pdum[2][2];

    for (int i = 0; i < 128; i++) {
        if (tid < 128) {
            sC0[tid] = make_float2(g_wz[(i << 7) + tid], bi[(i << 7) + tid]);
            sWf[tid] = Wf[(i << 7) + tid];
        }
        const float bfi = bf[i];
        const float* zg = g_zT + (size_t)i * Bn + b0;
        const int zr = mrow + gr0;
        float zA0 = zg[zr], zA1 = zg[zr + 8], zA2 = zg[zr + 16], zA3 = zg[zr + 24];
        __syncthreads();

        // G0
        gemm_ileave<0>(aOutA, aWiM, accA, accA, hA, sC0, sB12, sWf,
                       0.f, 0.f, 0.f, 0.f, pdum, lane, mrow, ncol);
        __syncthreads();
        if (i < 127) {
            const uint4* src = (const uint4*)(g_WiM + (size_t)(i + 1) * 16384);
            #pragma unroll
            for (int q = 0; q < 8; q++) {
                int v = (q << 8) + tid;
                cpa16(aWiM + (uint32_t)(v << 4), src + v);
            }
            asm volatile("cp.async.commit_group;");
        }
        // E0 -> H
        {
            const uint32_t xrE = (uint32_t)(gr0 << 4);
            #pragma unroll
            for (int nt = 0; nt < 8; nt++) {
                const int c = ncol + nt * 8 + gc0;
                float2 t0 = sC0[c], t1 = sC0[c + 1];
                const uint32_t cb = ((uint32_t)(2 * c)) ^ xrE;
                #pragma unroll
                for (int mt = 0; mt < 2; mt++) {
                    const int r0 = mrow + mt * 16 + gr0, r1 = r0 + 8;
                    const float zlo = mt ? zA2 : zA0, zhi = mt ? zA3 : zA1;
                    float v00 = fmaxf(fmaf(zlo, t0.x, accA[mt][nt][0]) + t0.y, 0.f);
                    float v01 = fmaxf(fmaf(zlo, t1.x, accA[mt][nt][1]) + t1.y, 0.f);
                    float v10 = fmaxf(fmaf(zhi, t0.x, accA[mt][nt][2]) + t0.y, 0.f);
                    float v11 = fmaxf(fmaf(zhi, t1.x, accA[mt][nt][3]) + t1.y, 0.f);
                    *(__half2*)(hA + r0 * 256 + cb) = __floats2half2_rn(v00, v01);
                    *(__half2*)(hA + r1 * 256 + cb) = __floats2half2_rn(v10, v11);
                }
            }
        }
        __syncthreads();
        // G1 + E1 in place
        gemm_ileave<0>(aHA, aW1, accA, accA, hA, sC0, sB12, sWf,
                       0.f, 0.f, 0.f, 0.f, pdum, lane, mrow, ncol);
        __syncthreads();
        {
            const uint32_t xrE = (uint32_t)(gr0 << 4);
            #pragma unroll
            for (int nt = 0; nt < 8; nt++) {
                const int c = ncol + nt * 8 + gc0;
                float q0 = sB12[c].x, q1 = sB12[c + 1].x;
                const uint32_t cb = ((uint32_t)(2 * c)) ^ xrE;
                #pragma unroll
                for (int mt = 0; mt < 2; mt++) {
                    const int r0 = mrow + mt * 16 + gr0, r1 = r0 + 8;
                    float v00 = fmaxf(accA[mt][nt][0] + q0, 0.f);
                    float v01 = fmaxf(accA[mt][nt][1] + q1, 0.f);
                    float v10 = fmaxf(accA[mt][nt][2] + q0, 0.f);
                    float v11 = fmaxf(accA[mt][nt][3] + q1, 0.f);
                    *(__half2*)(hA + r0 * 256 + cb) = __floats2half2_rn(v00, v01);
                    *(__half2*)(hA + r1 * 256 + cb) = __floats2half2_rn(v10, v11);
                }
            }
        }
        __syncthreads();
        // G2 + E2
        gemm_ileave<0>(aHA, aW2, accA, accA, hA, sC0, sB12, sWf,
                       0.f, 0.f, 0.f, 0.f, pdum, lane, mrow, ncol);
        {
            float p[2][2] = {{0.f, 0.f}, {0.f, 0.f}};
            #pragma unroll
            for (int nt = 0; nt < 8; nt++) {
                const int c = ncol + nt * 8 + gc0;
                const float wf0 = sWf[c], wf1 = sWf[c + 1];
                const float q0 = sB12[c].y, q1 = sB12[c + 1].y;
                #pragma unroll
                for (int mt = 0; mt < 2; mt++) {
                    p[mt][0] = fmaf(fmaxf(accA[mt][nt][0] + q0, 0.f), wf0,
                               fmaf(fmaxf(accA[mt][nt][1] + q1, 0.f), wf1, p[mt][0]));
                    p[mt][1] = fmaf(fmaxf(accA[mt][nt][2] + q0, 0.f), wf0,
                               fmaf(fmaxf(accA[mt][nt][3] + q1, 0.f), wf1, p[mt][1]));
                }
            }
            __syncthreads();
            #pragma unroll
            for (int mt = 0; mt < 2; mt++)
                #pragma unroll
                for (int h = 0; h < 2; h++) {
                    float v = p[mt][h];
                    v += __shfl_xor_sync(0xffffffffu, v, 1);
                    v += __shfl_xor_sync(0xffffffffu, v, 2);
                    if ((lane & 3) == 0)
                        sO2[wn * 128 + mrow + mt * 16 + h * 8 + gr0] = v;
                }
            __syncthreads();
            if (tid < 128) {
                float o = sO2[tid] + sO2[128 + tid] + bfi;
                out[(b0 + tid) * 128 + i] = o;
                *(__half*)(sm + OFF_OUTA + tile_off(tid, i)) = __float2half(o);
            }
        }
        if (i < 127) asm volatile("cp.async.wait_group 0;");
        __syncthreads();
    }
}

// ---- host ----
extern "C" void kernel_launch(void* const* d_in, const int* in_sizes, int n_in,
                              void* d_out, int out_size) {
    const float* x  = (const float*)d_in[0];
    const float* z  = (const float*)d_in[1];
    const float* M  = (const float*)d_in[2];
    const float* Wi = (const float*)d_in[3];
    const float* bi = (const float*)d_in[4];
    const float* Wf = (const float*)d_in[5];
    const float* bf = (const float*)d_in[6];
    const float* W1 = (const float*)d_in[7];
    const float* b1 = (const float*)d_in[8];
    const float* W2 = (const float*)d_in[9];
    const float* b2 = (const float*)d_in[10];
    int Bn = in_sizes[0] / 128;

    cudaFuncSetAttribute(gen_pair,   cudaFuncAttributeMaxDynamicSharedMemorySize, SMEM_TOTAL);
    cudaFuncSetAttribute(gen_single, cudaFuncAttributeMaxDynamicSharedMemorySize, SMEM_TOTAL);

    prep_weights<<<130, 256>>>(Wi, M, W1, W2);
    transpose_z<<<dim3(Bn / 32, 4), dim3(32, 8)>>>(z, Bn);

    int tiles = Bn / 128;                       // 1024
    int nPair = ((tiles / 2) / 148) * 148;      // 444 (3 full waves)
    int nSingle = tiles - 2 * nPair;            // 136 (1 partial wave)
    if (nPair > 0)
        gen_pair<<<nPair, 256, SMEM_TOTAL>>>(x, bi, Wf, bf, b1, b2, (float*)d_out, Bn, 0);
    if (nSingle > 0)
        gen_single<<<nSingle, 256, SMEM_TOTAL>>>(x, bi, Wf, bf, b1, b2, (float*)d_out, Bn, nPair * 256);
}